// round 7
// baseline (speedup 1.0000x reference)
#include <cuda_runtime.h>
#include <math.h>

#define B_ 2
#define S_ 2048
#define D_ 1024
#define H_ 16
#define HD_ 64

// ---------------- scratch ----------------
__device__ float g_ada[B_ * 6 * D_];
__device__ float g_h[(size_t)B_ * S_ * D_];
__device__ float g_qkv[(size_t)B_ * S_ * 3 * D_];
__device__ float g_attn2[(size_t)B_ * S_ * D_];
__device__ float g_x1[(size_t)B_ * S_ * D_];
__device__ float g_mlp[(size_t)B_ * S_ * 4 * D_];
// pre-rounded weights
__device__ float g_wqkv[(size_t)3 * D_ * D_];
__device__ float g_wout[(size_t)D_ * D_];
__device__ float g_w1[(size_t)4 * D_ * D_];
__device__ float g_w2[(size_t)4 * D_ * D_];

__device__ __forceinline__ unsigned f2tf(float f) {
    unsigned u;
    asm("cvt.rna.tf32.f32 %0, %1;" : "=r"(u) : "f"(f));
    return u;
}
// emulate RN for tf32: HW truncates low 13 bits, so +0x1000 = RN(ties up)
__device__ __forceinline__ float rndf(float v) {
    return __uint_as_float(__float_as_uint(v) + 0x1000u);
}

__device__ __forceinline__ float gelu_tanh(float v) {
    float u = 0.7978845608028654f * (v + 0.044715f * v * v * v);
    return 0.5f * v * (1.f + tanhf(u));
}

__device__ __forceinline__ void cp16(void* s, const void* g) {
    unsigned sa = (unsigned)__cvta_generic_to_shared(s);
    asm volatile("cp.async.cg.shared.global [%0], [%1], 16;" :: "r"(sa), "l"(g));
}
#define CP_COMMIT() asm volatile("cp.async.commit_group;")
#define CP_WAIT(n)  asm volatile("cp.async.wait_group %0;" :: "n"(n))

// ---------------- pre-round all 4 weight matrices in ONE launch ----------------
__global__ void round_all(const float* __restrict__ wq, const float* __restrict__ wo,
                          const float* __restrict__ w1, const float* __restrict__ w2,
                          float* __restrict__ oq, float* __restrict__ oo,
                          float* __restrict__ o1, float* __restrict__ o2)
{
    const long n_q = 3L * D_ * D_ / 4, n_o = (long)D_ * D_ / 4, n_m = (long)D_ * D_;
    long i = (long)blockIdx.x * 256 + threadIdx.x;
    const float* src; float* dst; long off;
    if (i < n_q)                    { src = wq; dst = oq; off = i; }
    else if (i < n_q + n_o)         { src = wo; dst = oo; off = i - n_q; }
    else if (i < n_q + n_o + n_m)   { src = w1; dst = o1; off = i - n_q - n_o; }
    else                            { src = w2; dst = o2; off = i - n_q - n_o - n_m; }
    float4 v = reinterpret_cast<const float4*>(src)[off];
    v.x = rndf(v.x); v.y = rndf(v.y); v.z = rndf(v.z); v.w = rndf(v.w);
    reinterpret_cast<float4*>(dst)[off] = v;
}

// ============================================================================
// Fused flash attention. qkv pre-rounded, Q pre-scaled by 1/8.
// 512 threads = 16 warps, Q tile 256 rows, key tiles of 64.
// ============================================================================
#define FA_SMEM 210944

__global__ void __launch_bounds__(512) flash_attn(
    const float* __restrict__ qkv, float* __restrict__ out)
{
    extern __shared__ unsigned sm[];
    unsigned* Qs  = sm;                     // [256][68]
    unsigned* Ks  = sm + 17408;             // [2][64][68]
    unsigned* Vs  = sm + 26112;             // [2][64][72]
    unsigned* Psw = sm + 35328;             // 16 x [16][68]

    const int tid  = threadIdx.x;
    const int lane = tid & 31;
    const int warp = tid >> 5;
    const int grp  = lane >> 2;
    const int tig  = lane & 3;
    const int b    = blockIdx.y >> 4;
    const int h    = blockIdx.y & 15;
    const int qBase = blockIdx.x * 256;

#pragma unroll
    for (int i = 0; i < 8; i++) {
        int idx = tid + i * 512;
        int r   = idx >> 4;
        int qd  = idx & 15;
        cp16(&Qs[r * 68 + qd * 4],
             &qkv[((long)(b * S_ + qBase + r)) * 3072 + h * 64 + qd * 4]);
    }
#pragma unroll
    for (int i = 0; i < 2; i++) {
        int idx = tid + i * 512;
        int r   = idx >> 4;
        int qd  = idx & 15;
        const float* base = &qkv[((long)(b * S_ + r)) * 3072 + h * 64 + qd * 4];
        cp16(&Ks[r * 68 + qd * 4], base + 1024);
        cp16(&Vs[r * 72 + qd * 4], base + 2048);
    }
    CP_COMMIT();

    unsigned* Ps = Psw + warp * 16 * 68;
    const unsigned* Qw = Qs + warp * 16 * 68;

    float m0 = -INFINITY, m1 = -INFINITY, l0 = 0.f, l1 = 0.f;
    float o[8][4];
#pragma unroll
    for (int j = 0; j < 8; j++)
#pragma unroll
        for (int t = 0; t < 4; t++) o[j][t] = 0.f;

    const int nT = S_ / 64;
    for (int t = 0; t < nT; t++) {
        CP_WAIT(0);
        __syncthreads();

        if (t + 1 < nT) {
            unsigned* Kn = Ks + ((t + 1) & 1) * 4352;
            unsigned* Vn = Vs + ((t + 1) & 1) * 4608;
            int kt = (t + 1) * 64;
#pragma unroll
            for (int i = 0; i < 2; i++) {
                int idx = tid + i * 512;
                int r   = idx >> 4;
                int qd  = idx & 15;
                const float* base = &qkv[((long)(b * S_ + kt + r)) * 3072 + h * 64 + qd * 4];
                cp16(&Kn[r * 68 + qd * 4], base + 1024);
                cp16(&Vn[r * 72 + qd * 4], base + 2048);
            }
        }
        CP_COMMIT();

        const unsigned* Kc = Ks + (t & 1) * 4352;
        const unsigned* Vc = Vs + (t & 1) * 4608;

        float s[8][4];
#pragma unroll
        for (int j = 0; j < 8; j++)
#pragma unroll
            for (int tt = 0; tt < 4; tt++) s[j][tt] = 0.f;

#pragma unroll
        for (int kk = 0; kk < 64; kk += 8) {
            unsigned a0 = Qw[grp * 68 + kk + tig];
            unsigned a1 = Qw[(grp + 8) * 68 + kk + tig];
            unsigned a2 = Qw[grp * 68 + kk + tig + 4];
            unsigned a3 = Qw[(grp + 8) * 68 + kk + tig + 4];
#pragma unroll
            for (int j = 0; j < 8; j++) {
                unsigned b0 = Kc[(j * 8 + grp) * 68 + kk + tig];
                unsigned b1 = Kc[(j * 8 + grp) * 68 + kk + tig + 4];
                asm volatile(
                    "mma.sync.aligned.m16n8k8.row.col.f32.tf32.tf32.f32 "
                    "{%0,%1,%2,%3}, {%4,%5,%6,%7}, {%8,%9}, {%0,%1,%2,%3};"
                    : "+f"(s[j][0]), "+f"(s[j][1]), "+f"(s[j][2]), "+f"(s[j][3])
                    : "r"(a0), "r"(a1), "r"(a2), "r"(a3), "r"(b0), "r"(b1));
            }
        }

        float mx0 = -INFINITY, mx1 = -INFINITY;
#pragma unroll
        for (int j = 0; j < 8; j++) {
            mx0 = fmaxf(mx0, fmaxf(s[j][0], s[j][1]));
            mx1 = fmaxf(mx1, fmaxf(s[j][2], s[j][3]));
        }
        mx0 = fmaxf(mx0, __shfl_xor_sync(0xffffffffu, mx0, 1));
        mx0 = fmaxf(mx0, __shfl_xor_sync(0xffffffffu, mx0, 2));
        mx1 = fmaxf(mx1, __shfl_xor_sync(0xffffffffu, mx1, 1));
        mx1 = fmaxf(mx1, __shfl_xor_sync(0xffffffffu, mx1, 2));
        float mn0 = fmaxf(m0, mx0), mn1 = fmaxf(m1, mx1);
        float sc0 = __expf(m0 - mn0), sc1 = __expf(m1 - mn1);

        float sum0 = 0.f, sum1 = 0.f;
#pragma unroll
        for (int j = 0; j < 8; j++) {
            float p0 = __expf(s[j][0] - mn0);
            float p1 = __expf(s[j][1] - mn0);
            float p2 = __expf(s[j][2] - mn1);
            float p3 = __expf(s[j][3] - mn1);
            sum0 += p0 + p1; sum1 += p2 + p3;
            Ps[grp * 68 + j * 8 + tig * 2]           = f2tf(p0);
            Ps[grp * 68 + j * 8 + tig * 2 + 1]       = f2tf(p1);
            Ps[(grp + 8) * 68 + j * 8 + tig * 2]     = f2tf(p2);
            Ps[(grp + 8) * 68 + j * 8 + tig * 2 + 1] = f2tf(p3);
        }
        sum0 += __shfl_xor_sync(0xffffffffu, sum0, 1);
        sum0 += __shfl_xor_sync(0xffffffffu, sum0, 2);
        sum1 += __shfl_xor_sync(0xffffffffu, sum1, 1);
        sum1 += __shfl_xor_sync(0xffffffffu, sum1, 2);
        l0 = l0 * sc0 + sum0;
        l1 = l1 * sc1 + sum1;
        m0 = mn0; m1 = mn1;

#pragma unroll
        for (int j = 0; j < 8; j++) {
            o[j][0] *= sc0; o[j][1] *= sc0;
            o[j][2] *= sc1; o[j][3] *= sc1;
        }
        __syncwarp();

#pragma unroll
        for (int kk = 0; kk < 64; kk += 8) {
            unsigned a0 = Ps[grp * 68 + kk + tig];
            unsigned a1 = Ps[(grp + 8) * 68 + kk + tig];
            unsigned a2 = Ps[grp * 68 + kk + tig + 4];
            unsigned a3 = Ps[(grp + 8) * 68 + kk + tig + 4];
#pragma unroll
            for (int j = 0; j < 8; j++) {
                unsigned b0 = Vc[(kk + tig) * 72 + j * 8 + grp];
                unsigned b1 = Vc[(kk + tig + 4) * 72 + j * 8 + grp];
                asm volatile(
                    "mma.sync.aligned.m16n8k8.row.col.f32.tf32.tf32.f32 "
                    "{%0,%1,%2,%3}, {%4,%5,%6,%7}, {%8,%9}, {%0,%1,%2,%3};"
                    : "+f"(o[j][0]), "+f"(o[j][1]), "+f"(o[j][2]), "+f"(o[j][3])
                    : "r"(a0), "r"(a1), "r"(a2), "r"(a3), "r"(b0), "r"(b1));
            }
        }
        __syncwarp();
    }

    float inv0 = 1.f / l0, inv1 = 1.f / l1;
    int row0 = qBase + warp * 16 + grp;
#pragma unroll
    for (int j = 0; j < 8; j++) {
        int col = h * 64 + j * 8 + tig * 2;
        float2 v0 = make_float2(rndf(o[j][0] * inv0), rndf(o[j][1] * inv0));
        *reinterpret_cast<float2*>(&out[((long)(b * S_ + row0)) * D_ + col]) = v0;
        float2 v1 = make_float2(rndf(o[j][2] * inv1), rndf(o[j][3] * inv1));
        *reinterpret_cast<float2*>(&out[((long)(b * S_ + row0 + 8)) * D_ + col]) = v1;
    }
}

// ============================================================================
// TF32 NT GEMM, 3-stage cp.async, 128 threads = 4 warps of 64x64 each
// (i=4 m16 tiles, j=8 n8 tiles -> 1.0 LDS per HMMA).
// Inputs pre-rounded. Epilogue modes as before.
// ============================================================================
#define GSTAGES 3
#define GEMM_SMEM (GSTAGES * 128 * 20 * 4 * 2)   // 61440 B

__global__ void __launch_bounds__(128) gemm_nt_tf32(
    const float* __restrict__ A, const float* __restrict__ B, float* __restrict__ C,
    int N, int K, int lda, int ldb, int ldc,
    int mode, const float* __restrict__ EX, const float* __restrict__ evec,
    const float* __restrict__ ada, int adaOff)
{
    extern __shared__ unsigned gsm[];
    unsigned* Asm = gsm;                         // [GSTAGES][128][20]
    unsigned* Bsm = gsm + GSTAGES * 128 * 20;

    const int tid   = threadIdx.x;
    const int lane  = tid & 31;
    const int warp  = tid >> 5;
    const int warpM = warp & 1;        // 2 warps along M
    const int warpN = warp >> 1;       // 2 warps along N
    const int grp   = lane >> 2;
    const int tig   = lane & 3;

    const int rowBase = blockIdx.y * 128;
    const int colBase = blockIdx.x * 128;

    float acc[4][8][4];
#pragma unroll
    for (int i = 0; i < 4; i++)
#pragma unroll
        for (int j = 0; j < 8; j++)
#pragma unroll
            for (int t = 0; t < 4; t++) acc[i][j][t] = 0.f;

    const int nCh = K >> 4;

    // loader: 128 threads, 4 float4 slots per matrix per chunk
    auto load_chunk = [&](int c, int st) {
        unsigned* as = Asm + st * 128 * 20;
        unsigned* bs = Bsm + st * 128 * 20;
#pragma unroll
        for (int it = 0; it < 4; it++) {
            int s = tid + it * 128;        // 0..511
            int r = s >> 2;
            int q = s & 3;
            cp16(&as[r * 20 + q * 4], A + (long)(rowBase + r) * lda + c * 16 + q * 4);
            cp16(&bs[r * 20 + q * 4], B + (long)(colBase + r) * ldb + c * 16 + q * 4);
        }
    };

#pragma unroll
    for (int s = 0; s < GSTAGES - 1; s++) {
        if (s < nCh) load_chunk(s, s);
        CP_COMMIT();
    }

    int st = 0;
    for (int c = 0; c < nCh; c++) {
        CP_WAIT(GSTAGES - 2);
        __syncthreads();

        int nc = c + GSTAGES - 1;
        if (nc < nCh) load_chunk(nc, nc % GSTAGES);
        CP_COMMIT();

        const unsigned* as = Asm + st * 128 * 20;
        const unsigned* bs = Bsm + st * 128 * 20;
#pragma unroll
        for (int kb = 0; kb < 2; kb++) {
            const int kk = kb * 8;
            unsigned af[4][4];
#pragma unroll
            for (int i = 0; i < 4; i++) {
                int r0 = warpM * 64 + i * 16 + grp;
                af[i][0] = as[r0 * 20 + kk + tig];
                af[i][1] = as[(r0 + 8) * 20 + kk + tig];
                af[i][2] = as[r0 * 20 + kk + tig + 4];
                af[i][3] = as[(r0 + 8) * 20 + kk + tig + 4];
            }
#pragma unroll
            for (int j = 0; j < 8; j++) {
                int c0 = warpN * 64 + j * 8 + grp;
                unsigned b0 = bs[c0 * 20 + kk + tig];
                unsigned b1 = bs[c0 * 20 + kk + tig + 4];
#pragma unroll
                for (int i = 0; i < 4; i++) {
                    asm volatile(
                        "mma.sync.aligned.m16n8k8.row.col.f32.tf32.tf32.f32 "
                        "{%0,%1,%2,%3}, {%4,%5,%6,%7}, {%8,%9}, {%0,%1,%2,%3};"
                        : "+f"(acc[i][j][0]), "+f"(acc[i][j][1]),
                          "+f"(acc[i][j][2]), "+f"(acc[i][j][3])
                        : "r"(af[i][0]), "r"(af[i][1]), "r"(af[i][2]), "r"(af[i][3]),
                          "r"(b0), "r"(b1));
                }
            }
        }
        st = (st + 1 == GSTAGES) ? 0 : st + 1;
    }

    // ---- epilogue ----
#pragma unroll
    for (int i = 0; i < 4; i++) {
#pragma unroll
        for (int j = 0; j < 8; j++) {
            long row = rowBase + warpM * 64 + i * 16 + grp;
            int col = colBase + warpN * 64 + j * 8 + tig * 2;
#pragma unroll
            for (int half = 0; half < 2; half++) {
                long r = row + half * 8;
                float v0 = acc[i][j][half * 2];
                float v1 = acc[i][j][half * 2 + 1];
                if (mode == 4) {
                    float qs = (col < 1024) ? 0.125f : 1.f;
                    v0 = rndf(v0 * qs);
                    v1 = rndf(v1 * qs);
                } else if (mode == 1) {
                    v0 = rndf(gelu_tanh(v0 + evec[col]));
                    v1 = rndf(gelu_tanh(v1 + evec[col + 1]));
                } else if (mode == 2) {
                    int bb = (int)(r >> 11);
                    v0 = EX[r * ldc + col] + ada[bb * 6 * D_ + adaOff + col] * v0;
                    v1 = EX[r * ldc + col + 1] + ada[bb * 6 * D_ + adaOff + col + 1] * v1;
                } else if (mode == 3) {
                    int bb = (int)(r >> 11);
                    v0 = EX[r * ldc + col] + ada[bb * 6 * D_ + adaOff + col] * (v0 + evec[col]);
                    v1 = EX[r * ldc + col + 1] + ada[bb * 6 * D_ + adaOff + col + 1] * (v1 + evec[col + 1]);
                }
                *reinterpret_cast<float2*>(&C[r * ldc + col]) = make_float2(v0, v1);
            }
        }
    }
}

// ---------------- adaLN ----------------
__global__ void __launch_bounds__(256) ada_kernel(
    const float* __restrict__ c, const float* __restrict__ w,
    const float* __restrict__ bias, float* __restrict__ out)
{
    int warp = (blockIdx.x * blockDim.x + threadIdx.x) >> 5;
    int lane = threadIdx.x & 31;
    if (warp >= 6 * D_) return;
    const float* wr = w + (long)warp * D_;
    float s0 = 0.f, s1 = 0.f;
    for (int d = lane; d < D_; d += 32) {
        float wv = wr[d];
        s0 += c[d] * wv;
        s1 += c[D_ + d] * wv;
    }
#pragma unroll
    for (int o = 16; o > 0; o >>= 1) {
        s0 += __shfl_down_sync(0xffffffffu, s0, o);
        s1 += __shfl_down_sync(0xffffffffu, s1, o);
    }
    if (lane == 0) {
        out[warp] = s0 + bias[warp];
        out[6 * D_ + warp] = s1 + bias[warp];
    }
}

// ---------------- LayerNorm + modulate (pre-rounded output) ----------------
__global__ void __launch_bounds__(256) ln_mod_kernel(
    const float* __restrict__ x, const float* __restrict__ w,
    const float* __restrict__ ada, int shOff, int scOff, float* __restrict__ h)
{
    int r = blockIdx.x;
    int b = r >> 11;
    const float* xr = x + (long)r * D_;
    int tid = threadIdx.x;
    float s = 0.f, ss = 0.f;
    float vals[4];
#pragma unroll
    for (int i = 0; i < 4; i++) {
        float v = xr[tid + i * 256];
        vals[i] = v; s += v; ss += v * v;
    }
    __shared__ float rs[256], rss[256];
    rs[tid] = s; rss[tid] = ss;
    __syncthreads();
    for (int st = 128; st > 0; st >>= 1) {
        if (tid < st) { rs[tid] += rs[tid + st]; rss[tid] += rss[tid + st]; }
        __syncthreads();
    }
    float mean = rs[0] * (1.f / D_);
    float var = rss[0] * (1.f / D_) - mean * mean;
    float inv = rsqrtf(var + 1e-5f);
    const float* sh = ada + b * 6 * D_ + shOff;
    const float* sc = ada + b * 6 * D_ + scOff;
#pragma unroll
    for (int i = 0; i < 4; i++) {
        int d = tid + i * 256;
        h[(long)r * D_ + d] = rndf((vals[i] - mean) * inv * w[d] * (1.f + sc[d]) + sh[d]);
    }
}

// ---------------- launch ----------------
extern "C" void kernel_launch(void* const* d_in, const int* in_sizes, int n_in,
                              void* d_out, int out_size)
{
    (void)in_sizes; (void)n_in; (void)out_size;
    const float* x       = (const float*)d_in[0];
    const float* c       = (const float*)d_in[3];
    const float* norm1_w = (const float*)d_in[4];
    const float* w_qkv   = (const float*)d_in[5];
    const float* w_out   = (const float*)d_in[6];
    const float* norm2_w = (const float*)d_in[7];
    const float* mlp_w1  = (const float*)d_in[8];
    const float* mlp_b1  = (const float*)d_in[9];
    const float* mlp_w2  = (const float*)d_in[10];
    const float* mlp_b2  = (const float*)d_in[11];
    const float* ada_w   = (const float*)d_in[12];
    const float* ada_b   = (const float*)d_in[13];
    float* out = (float*)d_out;

    float *ada, *h, *qkv, *attn2, *x1, *mlp, *wqkv_r, *wout_r, *w1_r, *w2_r;
    cudaGetSymbolAddress((void**)&ada,    g_ada);
    cudaGetSymbolAddress((void**)&h,      g_h);
    cudaGetSymbolAddress((void**)&qkv,    g_qkv);
    cudaGetSymbolAddress((void**)&attn2,  g_attn2);
    cudaGetSymbolAddress((void**)&x1,     g_x1);
    cudaGetSymbolAddress((void**)&mlp,    g_mlp);
    cudaGetSymbolAddress((void**)&wqkv_r, g_wqkv);
    cudaGetSymbolAddress((void**)&wout_r, g_wout);
    cudaGetSymbolAddress((void**)&w1_r,   g_w1);
    cudaGetSymbolAddress((void**)&w2_r,   g_w2);

    static int inited = 0;
    if (!inited) {
        cudaFuncSetAttribute(flash_attn, cudaFuncAttributeMaxDynamicSharedMemorySize, FA_SMEM);
        cudaFuncSetAttribute(gemm_nt_tf32, cudaFuncAttributeMaxDynamicSharedMemorySize, GEMM_SMEM);
        inited = 1;
    }

    // 0. pre-round all weights (single launch; 12*D*D/4 float4s)
    round_all<<<12 * D_ * D_ / 4 / 256, 256>>>(w_qkv, w_out, mlp_w1, mlp_w2,
                                               wqkv_r, wout_r, w1_r, w2_r);
    // 1. adaLN projection
    ada_kernel<<<768, 256>>>(c, ada_w, ada_b, ada);
    // 2. LN1 + modulate (rounded)
    ln_mod_kernel<<<B_ * S_, 256>>>(x, norm1_w, ada, 0, D_, h);
    // 3. QKV GEMM (epilogue: scale Q by 1/8, round)
    gemm_nt_tf32<<<dim3(24, 32), 128, GEMM_SMEM>>>(h, wqkv_r, qkv, 3 * D_, D_,
                                                   D_, D_, 3 * D_, 4,
                                                   nullptr, nullptr, nullptr, 0);
    // 4. flash attention -> attn2 (rounded)
    flash_attn<<<dim3(S_ / 256, B_ * H_), 512, FA_SMEM>>>(qkv, attn2);
    // 5. out-proj + residual1
    gemm_nt_tf32<<<dim3(8, 32), 128, GEMM_SMEM>>>(attn2, wout_r, x1, D_, D_,
                                                  D_, D_, D_, 2,
                                                  x, nullptr, ada, 2 * D_);
    // 6. LN2 + modulate (rounded)
    ln_mod_kernel<<<B_ * S_, 256>>>(x1, norm2_w, ada, 3 * D_, 4 * D_, h);
    // 7. MLP1 + bias + gelu (rounded)
    gemm_nt_tf32<<<dim3(32, 32), 128, GEMM_SMEM>>>(h, w1_r, mlp, 4 * D_, D_,
                                                   D_, D_, 4 * D_, 1,
                                                   nullptr, mlp_b1, nullptr, 0);
    // 8. MLP2 + final residual
    gemm_nt_tf32<<<dim3(8, 32), 128, GEMM_SMEM>>>(mlp, w2_r, out, D_, 4 * D_,
                                                  4 * D_, 4 * D_, D_, 3,
                                                  x1, mlp_b2, ada, 5 * D_);
}

// round 8
// speedup vs baseline: 1.5980x; 1.5980x over previous
#include <cuda_runtime.h>
#include <cuda_fp16.h>
#include <math.h>

#define B_ 2
#define S_ 2048
#define D_ 1024
#define H_ 16
#define HD_ 64

// ---------------- scratch ----------------
__device__ float  g_ada[B_ * 6 * D_];
__device__ __half g_h[(size_t)B_ * S_ * D_];                 // LN outputs (fp16)
__device__ float  g_qkv[(size_t)B_ * S_ * 3 * D_];           // fp32 (flash input)
__device__ __half g_attn2[(size_t)B_ * S_ * D_];             // flash output (fp16)
__device__ float  g_x1[(size_t)B_ * S_ * D_];
__device__ __half g_mlp[(size_t)B_ * S_ * 4 * D_];           // gelu output (fp16)
// fp16 weights
__device__ __half g_wqkv[(size_t)3 * D_ * D_];
__device__ __half g_wout[(size_t)D_ * D_];
__device__ __half g_w1[(size_t)4 * D_ * D_];
__device__ __half g_w2[(size_t)4 * D_ * D_];

__device__ __forceinline__ unsigned f2tf(float f) {
    unsigned u;
    asm("cvt.rna.tf32.f32 %0, %1;" : "=r"(u) : "f"(f));
    return u;
}
// emulate RN for tf32: HW truncates low 13 bits, so +0x1000 = RN(ties up)
__device__ __forceinline__ float rndf(float v) {
    return __uint_as_float(__float_as_uint(v) + 0x1000u);
}

__device__ __forceinline__ float gelu_tanh(float v) {
    float u = 0.7978845608028654f * (v + 0.044715f * v * v * v);
    return 0.5f * v * (1.f + tanhf(u));
}

__device__ __forceinline__ void cp16(void* s, const void* g) {
    unsigned sa = (unsigned)__cvta_generic_to_shared(s);
    asm volatile("cp.async.cg.shared.global [%0], [%1], 16;" :: "r"(sa), "l"(g));
}
#define CP_COMMIT() asm volatile("cp.async.commit_group;")
#define CP_WAIT(n)  asm volatile("cp.async.wait_group %0;" :: "n"(n))

// ---------------- convert weights fp32 -> fp16 ----------------
__global__ void conv_w(const float* __restrict__ s, __half* __restrict__ d, long n4)
{
    long i = (long)blockIdx.x * 256 + threadIdx.x;
    if (i >= n4) return;
    float4 v = reinterpret_cast<const float4*>(s)[i];
    __half2 h0 = __floats2half2_rn(v.x, v.y);
    __half2 h1 = __floats2half2_rn(v.z, v.w);
    reinterpret_cast<__half2*>(d)[i * 2]     = h0;
    reinterpret_cast<__half2*>(d)[i * 2 + 1] = h1;
}

// ============================================================================
// Fused flash attention (tf32 mma). qkv fp32, pre-rounded, Q pre-scaled 1/8.
// 512 threads = 16 warps, Q tile 256 rows, key tiles of 64. Output fp16.
// ============================================================================
#define FA_SMEM 210944

__global__ void __launch_bounds__(512) flash_attn(
    const float* __restrict__ qkv, __half* __restrict__ out)
{
    extern __shared__ unsigned sm[];
    unsigned* Qs  = sm;                     // [256][68]
    unsigned* Ks  = sm + 17408;             // [2][64][68]
    unsigned* Vs  = sm + 26112;             // [2][64][72]
    unsigned* Psw = sm + 35328;             // 16 x [16][68]

    const int tid  = threadIdx.x;
    const int lane = tid & 31;
    const int warp = tid >> 5;
    const int grp  = lane >> 2;
    const int tig  = lane & 3;
    const int b    = blockIdx.y >> 4;
    const int h    = blockIdx.y & 15;
    const int qBase = blockIdx.x * 256;

#pragma unroll
    for (int i = 0; i < 8; i++) {
        int idx = tid + i * 512;
        int r   = idx >> 4;
        int qd  = idx & 15;
        cp16(&Qs[r * 68 + qd * 4],
             &qkv[((long)(b * S_ + qBase + r)) * 3072 + h * 64 + qd * 4]);
    }
#pragma unroll
    for (int i = 0; i < 2; i++) {
        int idx = tid + i * 512;
        int r   = idx >> 4;
        int qd  = idx & 15;
        const float* base = &qkv[((long)(b * S_ + r)) * 3072 + h * 64 + qd * 4];
        cp16(&Ks[r * 68 + qd * 4], base + 1024);
        cp16(&Vs[r * 72 + qd * 4], base + 2048);
    }
    CP_COMMIT();

    unsigned* Ps = Psw + warp * 16 * 68;
    const unsigned* Qw = Qs + warp * 16 * 68;

    float m0 = -INFINITY, m1 = -INFINITY, l0 = 0.f, l1 = 0.f;
    float o[8][4];
#pragma unroll
    for (int j = 0; j < 8; j++)
#pragma unroll
        for (int t = 0; t < 4; t++) o[j][t] = 0.f;

    const int nT = S_ / 64;
    for (int t = 0; t < nT; t++) {
        CP_WAIT(0);
        __syncthreads();

        if (t + 1 < nT) {
            unsigned* Kn = Ks + ((t + 1) & 1) * 4352;
            unsigned* Vn = Vs + ((t + 1) & 1) * 4608;
            int kt = (t + 1) * 64;
#pragma unroll
            for (int i = 0; i < 2; i++) {
                int idx = tid + i * 512;
                int r   = idx >> 4;
                int qd  = idx & 15;
                const float* base = &qkv[((long)(b * S_ + kt + r)) * 3072 + h * 64 + qd * 4];
                cp16(&Kn[r * 68 + qd * 4], base + 1024);
                cp16(&Vn[r * 72 + qd * 4], base + 2048);
            }
        }
        CP_COMMIT();

        const unsigned* Kc = Ks + (t & 1) * 4352;
        const unsigned* Vc = Vs + (t & 1) * 4608;

        float s[8][4];
#pragma unroll
        for (int j = 0; j < 8; j++)
#pragma unroll
            for (int tt = 0; tt < 4; tt++) s[j][tt] = 0.f;

#pragma unroll
        for (int kk = 0; kk < 64; kk += 8) {
            unsigned a0 = Qw[grp * 68 + kk + tig];
            unsigned a1 = Qw[(grp + 8) * 68 + kk + tig];
            unsigned a2 = Qw[grp * 68 + kk + tig + 4];
            unsigned a3 = Qw[(grp + 8) * 68 + kk + tig + 4];
#pragma unroll
            for (int j = 0; j < 8; j++) {
                unsigned b0 = Kc[(j * 8 + grp) * 68 + kk + tig];
                unsigned b1 = Kc[(j * 8 + grp) * 68 + kk + tig + 4];
                asm volatile(
                    "mma.sync.aligned.m16n8k8.row.col.f32.tf32.tf32.f32 "
                    "{%0,%1,%2,%3}, {%4,%5,%6,%7}, {%8,%9}, {%0,%1,%2,%3};"
                    : "+f"(s[j][0]), "+f"(s[j][1]), "+f"(s[j][2]), "+f"(s[j][3])
                    : "r"(a0), "r"(a1), "r"(a2), "r"(a3), "r"(b0), "r"(b1));
            }
        }

        float mx0 = -INFINITY, mx1 = -INFINITY;
#pragma unroll
        for (int j = 0; j < 8; j++) {
            mx0 = fmaxf(mx0, fmaxf(s[j][0], s[j][1]));
            mx1 = fmaxf(mx1, fmaxf(s[j][2], s[j][3]));
        }
        mx0 = fmaxf(mx0, __shfl_xor_sync(0xffffffffu, mx0, 1));
        mx0 = fmaxf(mx0, __shfl_xor_sync(0xffffffffu, mx0, 2));
        mx1 = fmaxf(mx1, __shfl_xor_sync(0xffffffffu, mx1, 1));
        mx1 = fmaxf(mx1, __shfl_xor_sync(0xffffffffu, mx1, 2));
        float mn0 = fmaxf(m0, mx0), mn1 = fmaxf(m1, mx1);
        float sc0 = __expf(m0 - mn0), sc1 = __expf(m1 - mn1);

        float sum0 = 0.f, sum1 = 0.f;
#pragma unroll
        for (int j = 0; j < 8; j++) {
            float p0 = __expf(s[j][0] - mn0);
            float p1 = __expf(s[j][1] - mn0);
            float p2 = __expf(s[j][2] - mn1);
            float p3 = __expf(s[j][3] - mn1);
            sum0 += p0 + p1; sum1 += p2 + p3;
            Ps[grp * 68 + j * 8 + tig * 2]           = f2tf(p0);
            Ps[grp * 68 + j * 8 + tig * 2 + 1]       = f2tf(p1);
            Ps[(grp + 8) * 68 + j * 8 + tig * 2]     = f2tf(p2);
            Ps[(grp + 8) * 68 + j * 8 + tig * 2 + 1] = f2tf(p3);
        }
        sum0 += __shfl_xor_sync(0xffffffffu, sum0, 1);
        sum0 += __shfl_xor_sync(0xffffffffu, sum0, 2);
        sum1 += __shfl_xor_sync(0xffffffffu, sum1, 1);
        sum1 += __shfl_xor_sync(0xffffffffu, sum1, 2);
        l0 = l0 * sc0 + sum0;
        l1 = l1 * sc1 + sum1;
        m0 = mn0; m1 = mn1;

#pragma unroll
        for (int j = 0; j < 8; j++) {
            o[j][0] *= sc0; o[j][1] *= sc0;
            o[j][2] *= sc1; o[j][3] *= sc1;
        }
        __syncwarp();

#pragma unroll
        for (int kk = 0; kk < 64; kk += 8) {
            unsigned a0 = Ps[grp * 68 + kk + tig];
            unsigned a1 = Ps[(grp + 8) * 68 + kk + tig];
            unsigned a2 = Ps[grp * 68 + kk + tig + 4];
            unsigned a3 = Ps[(grp + 8) * 68 + kk + tig + 4];
#pragma unroll
            for (int j = 0; j < 8; j++) {
                unsigned b0 = Vc[(kk + tig) * 72 + j * 8 + grp];
                unsigned b1 = Vc[(kk + tig + 4) * 72 + j * 8 + grp];
                asm volatile(
                    "mma.sync.aligned.m16n8k8.row.col.f32.tf32.tf32.f32 "
                    "{%0,%1,%2,%3}, {%4,%5,%6,%7}, {%8,%9}, {%0,%1,%2,%3};"
                    : "+f"(o[j][0]), "+f"(o[j][1]), "+f"(o[j][2]), "+f"(o[j][3])
                    : "r"(a0), "r"(a1), "r"(a2), "r"(a3), "r"(b0), "r"(b1));
            }
        }
        __syncwarp();
    }

    // ---- normalize + store as fp16 (input to out-proj GEMM) ----
    float inv0 = 1.f / l0, inv1 = 1.f / l1;
    int row0 = qBase + warp * 16 + grp;
#pragma unroll
    for (int j = 0; j < 8; j++) {
        int col = h * 64 + j * 8 + tig * 2;
        __half2 v0 = __floats2half2_rn(o[j][0] * inv0, o[j][1] * inv0);
        *reinterpret_cast<__half2*>(&out[((long)(b * S_ + row0)) * D_ + col]) = v0;
        __half2 v1 = __floats2half2_rn(o[j][2] * inv1, o[j][3] * inv1);
        *reinterpret_cast<__half2*>(&out[((long)(b * S_ + row0 + 8)) * D_ + col]) = v1;
    }
}

// ============================================================================
// FP16 tensor-core NT GEMM (m16n8k16, fp32 accum), 3-stage cp.async.
// C[M,N] = epi(A[M,K] @ B[N,K]^T); A,B fp16; 256 threads, 8 warps of 64x32.
// K chunk = 32 halves. smem row stride 40 halves (conflict-free).
// mode 4: qkv -> float out, rndf(v * (col<1024 ? 1/8 : 1))
// mode 1: gelu(v + evec[col]) -> HALF out
// mode 2: EX + ada*v -> float out
// mode 3: EX + ada*(v + evec) -> float out
// ============================================================================
#define GSTAGES 3
#define GEMM_SMEM (GSTAGES * 128 * 40 * 2 * 2)   // 61440 B

__global__ void __launch_bounds__(256) gemm_nt_f16(
    const __half* __restrict__ A, const __half* __restrict__ B, void* __restrict__ Cv,
    int K, int lda, int ldb, int ldc,
    int mode, const float* __restrict__ EX, const float* __restrict__ evec,
    const float* __restrict__ ada, int adaOff)
{
    extern __shared__ __half hsm[];
    __half* Asm = hsm;                           // [GSTAGES][128][40]
    __half* Bsm = hsm + GSTAGES * 128 * 40;

    const int tid   = threadIdx.x;
    const int lane  = tid & 31;
    const int warp  = tid >> 5;
    const int warpM = warp & 1;
    const int warpN = warp >> 1;
    const int grp   = lane >> 2;
    const int tig   = lane & 3;

    const int rowBase = blockIdx.y * 128;
    const int colBase = blockIdx.x * 128;

    float acc[4][4][4];
#pragma unroll
    for (int i = 0; i < 4; i++)
#pragma unroll
        for (int j = 0; j < 4; j++)
#pragma unroll
            for (int t = 0; t < 4; t++) acc[i][j][t] = 0.f;

    const int nCh = K >> 5;                      // 32 halves per chunk

    auto load_chunk = [&](int c, int st) {
        __half* as = Asm + st * 128 * 40;
        __half* bs = Bsm + st * 128 * 40;
#pragma unroll
        for (int it = 0; it < 2; it++) {
            int s = tid + it * 256;              // 0..511
            int r = s >> 2;                      // 0..127
            int q = s & 3;                       // 8-half group
            cp16(&as[r * 40 + q * 8], A + (long)(rowBase + r) * lda + c * 32 + q * 8);
            cp16(&bs[r * 40 + q * 8], B + (long)(colBase + r) * ldb + c * 32 + q * 8);
        }
    };

#pragma unroll
    for (int s = 0; s < GSTAGES - 1; s++) {
        if (s < nCh) load_chunk(s, s);
        CP_COMMIT();
    }

    int st = 0;
    for (int c = 0; c < nCh; c++) {
        CP_WAIT(GSTAGES - 2);
        __syncthreads();

        int nc = c + GSTAGES - 1;
        if (nc < nCh) load_chunk(nc, nc % GSTAGES);
        CP_COMMIT();

        const __half* as = Asm + st * 128 * 40;
        const __half* bs = Bsm + st * 128 * 40;
#pragma unroll
        for (int kb = 0; kb < 2; kb++) {
            const int kk = kb * 16;
            unsigned af[4][4], bfr[4][2];
#pragma unroll
            for (int i = 0; i < 4; i++) {
                int r0 = warpM * 64 + i * 16 + grp;
                af[i][0] = *reinterpret_cast<const unsigned*>(&as[r0 * 40 + kk + tig * 2]);
                af[i][1] = *reinterpret_cast<const unsigned*>(&as[(r0 + 8) * 40 + kk + tig * 2]);
                af[i][2] = *reinterpret_cast<const unsigned*>(&as[r0 * 40 + kk + 8 + tig * 2]);
                af[i][3] = *reinterpret_cast<const unsigned*>(&as[(r0 + 8) * 40 + kk + 8 + tig * 2]);
            }
#pragma unroll
            for (int j = 0; j < 4; j++) {
                int c0 = warpN * 32 + j * 8 + grp;
                bfr[j][0] = *reinterpret_cast<const unsigned*>(&bs[c0 * 40 + kk + tig * 2]);
                bfr[j][1] = *reinterpret_cast<const unsigned*>(&bs[c0 * 40 + kk + 8 + tig * 2]);
            }
#pragma unroll
            for (int i = 0; i < 4; i++)
#pragma unroll
                for (int j = 0; j < 4; j++) {
                    asm volatile(
                        "mma.sync.aligned.m16n8k16.row.col.f32.f16.f16.f32 "
                        "{%0,%1,%2,%3}, {%4,%5,%6,%7}, {%8,%9}, {%0,%1,%2,%3};"
                        : "+f"(acc[i][j][0]), "+f"(acc[i][j][1]),
                          "+f"(acc[i][j][2]), "+f"(acc[i][j][3])
                        : "r"(af[i][0]), "r"(af[i][1]), "r"(af[i][2]), "r"(af[i][3]),
                          "r"(bfr[j][0]), "r"(bfr[j][1]));
                }
        }
        st = (st + 1 == GSTAGES) ? 0 : st + 1;
    }

    // ---- epilogue ----
    float* Cf = (float*)Cv;
    __half* Ch = (__half*)Cv;
#pragma unroll
    for (int i = 0; i < 4; i++) {
#pragma unroll
        for (int j = 0; j < 4; j++) {
            long row = rowBase + warpM * 64 + i * 16 + grp;
            int col = colBase + warpN * 32 + j * 8 + tig * 2;
#pragma unroll
            for (int half_ = 0; half_ < 2; half_++) {
                long r = row + half_ * 8;
                float v0 = acc[i][j][half_ * 2];
                float v1 = acc[i][j][half_ * 2 + 1];
                if (mode == 4) {
                    float qs = (col < 1024) ? 0.125f : 1.f;
                    *reinterpret_cast<float2*>(&Cf[r * ldc + col]) =
                        make_float2(rndf(v0 * qs), rndf(v1 * qs));
                } else if (mode == 1) {
                    __half2 hv = __floats2half2_rn(gelu_tanh(v0 + evec[col]),
                                                   gelu_tanh(v1 + evec[col + 1]));
                    *reinterpret_cast<__half2*>(&Ch[r * ldc + col]) = hv;
                } else if (mode == 2) {
                    int bb = (int)(r >> 11);
                    v0 = EX[r * ldc + col] + ada[bb * 6 * D_ + adaOff + col] * v0;
                    v1 = EX[r * ldc + col + 1] + ada[bb * 6 * D_ + adaOff + col + 1] * v1;
                    *reinterpret_cast<float2*>(&Cf[r * ldc + col]) = make_float2(v0, v1);
                } else {  // mode 3
                    int bb = (int)(r >> 11);
                    v0 = EX[r * ldc + col] + ada[bb * 6 * D_ + adaOff + col] * (v0 + evec[col]);
                    v1 = EX[r * ldc + col + 1] + ada[bb * 6 * D_ + adaOff + col + 1] * (v1 + evec[col + 1]);
                    *reinterpret_cast<float2*>(&Cf[r * ldc + col]) = make_float2(v0, v1);
                }
            }
        }
    }
}

// ---------------- adaLN ----------------
__global__ void __launch_bounds__(256) ada_kernel(
    const float* __restrict__ c, const float* __restrict__ w,
    const float* __restrict__ bias, float* __restrict__ out)
{
    int warp = (blockIdx.x * blockDim.x + threadIdx.x) >> 5;
    int lane = threadIdx.x & 31;
    if (warp >= 6 * D_) return;
    const float* wr = w + (long)warp * D_;
    float s0 = 0.f, s1 = 0.f;
    for (int d = lane; d < D_; d += 32) {
        float wv = wr[d];
        s0 += c[d] * wv;
        s1 += c[D_ + d] * wv;
    }
#pragma unroll
    for (int o = 16; o > 0; o >>= 1) {
        s0 += __shfl_down_sync(0xffffffffu, s0, o);
        s1 += __shfl_down_sync(0xffffffffu, s1, o);
    }
    if (lane == 0) {
        out[warp] = s0 + bias[warp];
        out[6 * D_ + warp] = s1 + bias[warp];
    }
}

// ---------------- LayerNorm + modulate, fp16 output ----------------
__global__ void __launch_bounds__(256) ln_mod_kernel(
    const float* __restrict__ x, const float* __restrict__ w,
    const float* __restrict__ ada, int shOff, int scOff, __half* __restrict__ h)
{
    int r = blockIdx.x;
    int b = r >> 11;
    const float* xr = x + (long)r * D_;
    int tid = threadIdx.x;
    float s = 0.f, ss = 0.f;
    float vals[4];
#pragma unroll
    for (int i = 0; i < 4; i++) {
        float v = xr[tid + i * 256];
        vals[i] = v; s += v; ss += v * v;
    }
    __shared__ float rs[256], rss[256];
    rs[tid] = s; rss[tid] = ss;
    __syncthreads();
    for (int st = 128; st > 0; st >>= 1) {
        if (tid < st) { rs[tid] += rs[tid + st]; rss[tid] += rss[tid + st]; }
        __syncthreads();
    }
    float mean = rs[0] * (1.f / D_);
    float var = rss[0] * (1.f / D_) - mean * mean;
    float inv = rsqrtf(var + 1e-5f);
    const float* sh = ada + b * 6 * D_ + shOff;
    const float* sc = ada + b * 6 * D_ + scOff;
#pragma unroll
    for (int i = 0; i < 4; i++) {
        int d = tid + i * 256;
        h[(long)r * D_ + d] =
            __float2half_rn((vals[i] - mean) * inv * w[d] * (1.f + sc[d]) + sh[d]);
    }
}

// ---------------- launch ----------------
extern "C" void kernel_launch(void* const* d_in, const int* in_sizes, int n_in,
                              void* d_out, int out_size)
{
    (void)in_sizes; (void)n_in; (void)out_size;
    const float* x       = (const float*)d_in[0];
    const float* c       = (const float*)d_in[3];
    const float* norm1_w = (const float*)d_in[4];
    const float* w_qkv   = (const float*)d_in[5];
    const float* w_out   = (const float*)d_in[6];
    const float* norm2_w = (const float*)d_in[7];
    const float* mlp_w1  = (const float*)d_in[8];
    const float* mlp_b1  = (const float*)d_in[9];
    const float* mlp_w2  = (const float*)d_in[10];
    const float* mlp_b2  = (const float*)d_in[11];
    const float* ada_w   = (const float*)d_in[12];
    const float* ada_b   = (const float*)d_in[13];
    float* out = (float*)d_out;

    float *ada, *qkv, *x1;
    __half *h, *attn2, *mlp, *wqkv_h, *wout_h, *w1_h, *w2_h;
    cudaGetSymbolAddress((void**)&ada,    g_ada);
    cudaGetSymbolAddress((void**)&h,      g_h);
    cudaGetSymbolAddress((void**)&qkv,    g_qkv);
    cudaGetSymbolAddress((void**)&attn2,  g_attn2);
    cudaGetSymbolAddress((void**)&x1,     g_x1);
    cudaGetSymbolAddress((void**)&mlp,    g_mlp);
    cudaGetSymbolAddress((void**)&wqkv_h, g_wqkv);
    cudaGetSymbolAddress((void**)&wout_h, g_wout);
    cudaGetSymbolAddress((void**)&w1_h,   g_w1);
    cudaGetSymbolAddress((void**)&w2_h,   g_w2);

    static int inited = 0;
    if (!inited) {
        cudaFuncSetAttribute(flash_attn, cudaFuncAttributeMaxDynamicSharedMemorySize, FA_SMEM);
        cudaFuncSetAttribute(gemm_nt_f16, cudaFuncAttributeMaxDynamicSharedMemorySize, GEMM_SMEM);
        inited = 1;
    }

    // 0. convert weights to fp16
    conv_w<<<(3 * D_ * D_ / 4 + 255) / 256, 256>>>(w_qkv, wqkv_h, 3L * D_ * D_ / 4);
    conv_w<<<(D_ * D_ / 4 + 255) / 256, 256>>>(w_out, wout_h, (long)D_ * D_ / 4);
    conv_w<<<(4 * D_ * D_ / 4 + 255) / 256, 256>>>(mlp_w1, w1_h, 4L * D_ * D_ / 4);
    conv_w<<<(4 * D_ * D_ / 4 + 255) / 256, 256>>>(mlp_w2, w2_h, 4L * D_ * D_ / 4);
    // 1. adaLN projection
    ada_kernel<<<768, 256>>>(c, ada_w, ada_b, ada);
    // 2. LN1 + modulate -> fp16 h
    ln_mod_kernel<<<B_ * S_, 256>>>(x, norm1_w, ada, 0, D_, h);
    // 3. QKV GEMM (fp16 in, fp32 out; Q scaled 1/8, tf32-rounded for flash)
    gemm_nt_f16<<<dim3(24, 32), 256, GEMM_SMEM>>>(h, wqkv_h, qkv, D_,
                                                  D_, D_, 3 * D_, 4,
                                                  nullptr, nullptr, nullptr, 0);
    // 4. flash attention -> attn2 (fp16)
    flash_attn<<<dim3(S_ / 256, B_ * H_), 512, FA_SMEM>>>(qkv, attn2);
    // 5. out-proj + residual1 (fp32 out)
    gemm_nt_f16<<<dim3(8, 32), 256, GEMM_SMEM>>>(attn2, wout_h, x1, D_,
                                                 D_, D_, D_, 2,
                                                 x, nullptr, ada, 2 * D_);
    // 6. LN2 + modulate -> fp16 h
    ln_mod_kernel<<<B_ * S_, 256>>>(x1, norm2_w, ada, 3 * D_, 4 * D_, h);
    // 7. MLP1 + bias + gelu -> fp16 mlp
    gemm_nt_f16<<<dim3(32, 32), 256, GEMM_SMEM>>>(h, w1_h, mlp, D_,
                                                  D_, D_, 4 * D_, 1,
                                                  nullptr, mlp_b1, nullptr, 0);
    // 8. MLP2 + final residual (fp32 out)
    gemm_nt_f16<<<dim3(8, 32), 256, GEMM_SMEM>>>(mlp, w2_h, out, 4 * D_,
                                                 4 * D_, 4 * D_, D_, 3,
                                                 x1, mlp_b2, ada, 5 * D_);
}

// round 9
// speedup vs baseline: 1.9307x; 1.2081x over previous
#include <cuda_runtime.h>
#include <cuda_fp16.h>
#include <math.h>

#define B_ 2
#define S_ 2048
#define D_ 1024
#define H_ 16
#define HD_ 64

// ---------------- scratch ----------------
__device__ float  g_ada[B_ * 6 * D_];
__device__ __half g_h[(size_t)B_ * S_ * D_];                 // LN outputs (fp16)
__device__ __half g_qkh[(size_t)B_ * S_ * 2 * D_];           // Q(scaled),K fp16 [B,S,2048]
__device__ __half g_vt[(size_t)B_ * H_ * HD_ * S_];          // V^T fp16 [B,H,HD,S]
__device__ __half g_attn2[(size_t)B_ * S_ * D_];             // flash output (fp16)
__device__ float  g_x1[(size_t)B_ * S_ * D_];
__device__ __half g_mlp[(size_t)B_ * S_ * 4 * D_];           // gelu output (fp16)
// fp16 weights
__device__ __half g_wqkv[(size_t)3 * D_ * D_];
__device__ __half g_wout[(size_t)D_ * D_];
__device__ __half g_w1[(size_t)4 * D_ * D_];
__device__ __half g_w2[(size_t)4 * D_ * D_];

__device__ __forceinline__ float gelu_tanh(float v) {
    float u = 0.7978845608028654f * (v + 0.044715f * v * v * v);
    return 0.5f * v * (1.f + tanhf(u));
}

__device__ __forceinline__ void cp16(void* s, const void* g) {
    unsigned sa = (unsigned)__cvta_generic_to_shared(s);
    asm volatile("cp.async.cg.shared.global [%0], [%1], 16;" :: "r"(sa), "l"(g));
}
#define CP_COMMIT() asm volatile("cp.async.commit_group;")
#define CP_WAIT(n)  asm volatile("cp.async.wait_group %0;" :: "n"(n))

#define MMA16(d0,d1,d2,d3,a0,a1,a2,a3,b0,b1) \
    asm volatile( \
        "mma.sync.aligned.m16n8k16.row.col.f32.f16.f16.f32 " \
        "{%0,%1,%2,%3}, {%4,%5,%6,%7}, {%8,%9}, {%0,%1,%2,%3};" \
        : "+f"(d0), "+f"(d1), "+f"(d2), "+f"(d3) \
        : "r"(a0), "r"(a1), "r"(a2), "r"(a3), "r"(b0), "r"(b1))

// ---------------- convert all weights fp32 -> fp16 (one launch) ----------------
__global__ void conv_all(const float* __restrict__ wq, const float* __restrict__ wo,
                         const float* __restrict__ w1, const float* __restrict__ w2,
                         __half* __restrict__ oq, __half* __restrict__ oo,
                         __half* __restrict__ o1, __half* __restrict__ o2)
{
    const long n_q = 3L * D_ * D_ / 4, n_o = (long)D_ * D_ / 4, n_m = (long)D_ * D_;
    long i = (long)blockIdx.x * 256 + threadIdx.x;
    const float* src; __half* dst; long off;
    if (i < n_q)                  { src = wq; dst = oq; off = i; }
    else if (i < n_q + n_o)       { src = wo; dst = oo; off = i - n_q; }
    else if (i < n_q + n_o + n_m) { src = w1; dst = o1; off = i - n_q - n_o; }
    else                          { src = w2; dst = o2; off = i - n_q - n_o - n_m; }
    float4 v = reinterpret_cast<const float4*>(src)[off];
    reinterpret_cast<__half2*>(dst)[off * 2]     = __floats2half2_rn(v.x, v.y);
    reinterpret_cast<__half2*>(dst)[off * 2 + 1] = __floats2half2_rn(v.z, v.w);
}

// ============================================================================
// Fused flash attention, fp16 mma (m16n8k16), online softmax.
// qkh: [B,S,2048] fp16 (Q pre-scaled 1/8, K). vt: [B,H,64,2048] fp16.
// 512 threads = 16 warps, Q tile 256 rows, key tiles of 64. Output fp16.
// smem halves: Q[256][72]=18432 | K 2x[64][72]=9216 | Vt 2x[64][72]=9216 |
//              P 16x[16][72]=18432  -> 55296 halves = 110592 B
// ============================================================================
#define FA_SMEM 110592

__global__ void __launch_bounds__(512) flash_attn(
    const __half* __restrict__ qkh, const __half* __restrict__ vt,
    __half* __restrict__ out)
{
    extern __shared__ __half sm[];
    __half* Qs  = sm;                       // [256][72]
    __half* Ks  = sm + 18432;               // [2][64][72]
    __half* Vs  = sm + 27648;               // [2][64][72]  (V^T: row=hd, col=key)
    __half* Psw = sm + 36864;               // 16 x [16][72]

    const int tid  = threadIdx.x;
    const int lane = tid & 31;
    const int warp = tid >> 5;
    const int grp  = lane >> 2;
    const int tig  = lane & 3;
    const int b    = blockIdx.y >> 4;
    const int h    = blockIdx.y & 15;
    const int qBase = blockIdx.x * 256;

    const __half* vth = vt + ((long)(b * H_ + h) * HD_) * S_;

    // ---- prologue: Q tile (256 rows x 64 halves) + K/Vt tile 0 ----
#pragma unroll
    for (int i = 0; i < 4; i++) {
        int idx = tid + i * 512;            // 0..2047
        int r   = idx >> 3;                 // 0..255
        int q8  = idx & 7;
        cp16(&Qs[r * 72 + q8 * 8],
             &qkh[((long)(b * S_ + qBase + r)) * 2048 + h * 64 + q8 * 8]);
    }
    {
        int r  = tid >> 3;                  // 0..63
        int q8 = tid & 7;
        cp16(&Ks[r * 72 + q8 * 8],
             &qkh[((long)(b * S_ + r)) * 2048 + 1024 + h * 64 + q8 * 8]);
        cp16(&Vs[r * 72 + q8 * 8], &vth[(long)r * S_ + q8 * 8]);
    }
    CP_COMMIT();

    __half* Ps = Psw + warp * 16 * 72;
    const __half* Qw = Qs + warp * 16 * 72;

    float m0 = -INFINITY, m1 = -INFINITY, l0 = 0.f, l1 = 0.f;
    float o[8][4];
#pragma unroll
    for (int j = 0; j < 8; j++)
#pragma unroll
        for (int t = 0; t < 4; t++) o[j][t] = 0.f;

    const int nT = S_ / 64;
    for (int t = 0; t < nT; t++) {
        CP_WAIT(0);
        __syncthreads();

        if (t + 1 < nT) {
            __half* Kn = Ks + ((t + 1) & 1) * 4608;
            __half* Vn = Vs + ((t + 1) & 1) * 4608;
            int kt = (t + 1) * 64;
            int r  = tid >> 3;
            int q8 = tid & 7;
            cp16(&Kn[r * 72 + q8 * 8],
                 &qkh[((long)(b * S_ + kt + r)) * 2048 + 1024 + h * 64 + q8 * 8]);
            cp16(&Vn[r * 72 + q8 * 8], &vth[(long)r * S_ + kt + q8 * 8]);
        }
        CP_COMMIT();

        const __half* Kc = Ks + (t & 1) * 4608;
        const __half* Vc = Vs + (t & 1) * 4608;

        // ---- scores = Q @ K^T (fp16, Q pre-scaled) ----
        float s[8][4];
#pragma unroll
        for (int j = 0; j < 8; j++)
#pragma unroll
            for (int tt = 0; tt < 4; tt++) s[j][tt] = 0.f;

#pragma unroll
        for (int kk = 0; kk < 64; kk += 16) {
            unsigned a0 = *reinterpret_cast<const unsigned*>(&Qw[grp * 72 + kk + tig * 2]);
            unsigned a1 = *reinterpret_cast<const unsigned*>(&Qw[(grp + 8) * 72 + kk + tig * 2]);
            unsigned a2 = *reinterpret_cast<const unsigned*>(&Qw[grp * 72 + kk + 8 + tig * 2]);
            unsigned a3 = *reinterpret_cast<const unsigned*>(&Qw[(grp + 8) * 72 + kk + 8 + tig * 2]);
#pragma unroll
            for (int j = 0; j < 8; j++) {
                int c0 = j * 8 + grp;
                unsigned b0 = *reinterpret_cast<const unsigned*>(&Kc[c0 * 72 + kk + tig * 2]);
                unsigned b1 = *reinterpret_cast<const unsigned*>(&Kc[c0 * 72 + kk + 8 + tig * 2]);
                MMA16(s[j][0], s[j][1], s[j][2], s[j][3], a0, a1, a2, a3, b0, b1);
            }
        }

        // ---- online softmax ----
        float mx0 = -INFINITY, mx1 = -INFINITY;
#pragma unroll
        for (int j = 0; j < 8; j++) {
            mx0 = fmaxf(mx0, fmaxf(s[j][0], s[j][1]));
            mx1 = fmaxf(mx1, fmaxf(s[j][2], s[j][3]));
        }
        mx0 = fmaxf(mx0, __shfl_xor_sync(0xffffffffu, mx0, 1));
        mx0 = fmaxf(mx0, __shfl_xor_sync(0xffffffffu, mx0, 2));
        mx1 = fmaxf(mx1, __shfl_xor_sync(0xffffffffu, mx1, 1));
        mx1 = fmaxf(mx1, __shfl_xor_sync(0xffffffffu, mx1, 2));
        float mn0 = fmaxf(m0, mx0), mn1 = fmaxf(m1, mx1);
        float sc0 = __expf(m0 - mn0), sc1 = __expf(m1 - mn1);

        float sum0 = 0.f, sum1 = 0.f;
#pragma unroll
        for (int j = 0; j < 8; j++) {
            float p0 = __expf(s[j][0] - mn0);
            float p1 = __expf(s[j][1] - mn0);
            float p2 = __expf(s[j][2] - mn1);
            float p3 = __expf(s[j][3] - mn1);
            sum0 += p0 + p1; sum1 += p2 + p3;
            *reinterpret_cast<__half2*>(&Ps[grp * 72 + j * 8 + tig * 2]) =
                __floats2half2_rn(p0, p1);
            *reinterpret_cast<__half2*>(&Ps[(grp + 8) * 72 + j * 8 + tig * 2]) =
                __floats2half2_rn(p2, p3);
        }
        sum0 += __shfl_xor_sync(0xffffffffu, sum0, 1);
        sum0 += __shfl_xor_sync(0xffffffffu, sum0, 2);
        sum1 += __shfl_xor_sync(0xffffffffu, sum1, 1);
        sum1 += __shfl_xor_sync(0xffffffffu, sum1, 2);
        l0 = l0 * sc0 + sum0;
        l1 = l1 * sc1 + sum1;
        m0 = mn0; m1 = mn1;

#pragma unroll
        for (int j = 0; j < 8; j++) {
            o[j][0] *= sc0; o[j][1] *= sc0;
            o[j][2] *= sc1; o[j][3] *= sc1;
        }
        __syncwarp();

        // ---- O += P @ V  (Vt layout: B-fragment identical to K pattern) ----
#pragma unroll
        for (int kk = 0; kk < 64; kk += 16) {
            unsigned a0 = *reinterpret_cast<const unsigned*>(&Ps[grp * 72 + kk + tig * 2]);
            unsigned a1 = *reinterpret_cast<const unsigned*>(&Ps[(grp + 8) * 72 + kk + tig * 2]);
            unsigned a2 = *reinterpret_cast<const unsigned*>(&Ps[grp * 72 + kk + 8 + tig * 2]);
            unsigned a3 = *reinterpret_cast<const unsigned*>(&Ps[(grp + 8) * 72 + kk + 8 + tig * 2]);
#pragma unroll
            for (int j = 0; j < 8; j++) {
                int c0 = j * 8 + grp;          // hd index
                unsigned b0 = *reinterpret_cast<const unsigned*>(&Vc[c0 * 72 + kk + tig * 2]);
                unsigned b1 = *reinterpret_cast<const unsigned*>(&Vc[c0 * 72 + kk + 8 + tig * 2]);
                MMA16(o[j][0], o[j][1], o[j][2], o[j][3], a0, a1, a2, a3, b0, b1);
            }
        }
        __syncwarp();
    }

    // ---- normalize + store fp16 ----
    float inv0 = 1.f / l0, inv1 = 1.f / l1;
    int row0 = qBase + warp * 16 + grp;
#pragma unroll
    for (int j = 0; j < 8; j++) {
        int col = h * 64 + j * 8 + tig * 2;
        *reinterpret_cast<__half2*>(&out[((long)(b * S_ + row0)) * D_ + col]) =
            __floats2half2_rn(o[j][0] * inv0, o[j][1] * inv0);
        *reinterpret_cast<__half2*>(&out[((long)(b * S_ + row0 + 8)) * D_ + col]) =
            __floats2half2_rn(o[j][2] * inv1, o[j][3] * inv1);
    }
}

// ============================================================================
// FP16 tensor-core NT GEMM (m16n8k16, fp32 accum), 3-stage cp.async.
// 256 threads, 8 warps of 64x32.
// mode 4: qkv split -> Q(x1/8),K to qh fp16 [.,2048]; V transposed to vth
// mode 1: gelu(v + evec[col]) -> HALF out
// mode 2: EX + ada*v -> float out
// mode 3: EX + ada*(v + evec) -> float out
// ============================================================================
#define GSTAGES 3
#define GEMM_SMEM (GSTAGES * 128 * 40 * 2 * 2)   // 61440 B

__global__ void __launch_bounds__(256) gemm_nt_f16(
    const __half* __restrict__ A, const __half* __restrict__ B, void* __restrict__ Cv,
    int K, int lda, int ldb, int ldc,
    int mode, const float* __restrict__ EX, const float* __restrict__ evec,
    const float* __restrict__ ada, int adaOff,
    __half* __restrict__ qh, __half* __restrict__ vth)
{
    extern __shared__ __half hsm[];
    __half* Asm = hsm;                           // [GSTAGES][128][40]
    __half* Bsm = hsm + GSTAGES * 128 * 40;

    const int tid   = threadIdx.x;
    const int lane  = tid & 31;
    const int warp  = tid >> 5;
    const int warpM = warp & 1;
    const int warpN = warp >> 1;
    const int grp   = lane >> 2;
    const int tig   = lane & 3;

    const int rowBase = blockIdx.y * 128;
    const int colBase = blockIdx.x * 128;

    float acc[4][4][4];
#pragma unroll
    for (int i = 0; i < 4; i++)
#pragma unroll
        for (int j = 0; j < 4; j++)
#pragma unroll
            for (int t = 0; t < 4; t++) acc[i][j][t] = 0.f;

    const int nCh = K >> 5;

    auto load_chunk = [&](int c, int st) {
        __half* as = Asm + st * 128 * 40;
        __half* bs = Bsm + st * 128 * 40;
#pragma unroll
        for (int it = 0; it < 2; it++) {
            int s = tid + it * 256;
            int r = s >> 2;
            int q = s & 3;
            cp16(&as[r * 40 + q * 8], A + (long)(rowBase + r) * lda + c * 32 + q * 8);
            cp16(&bs[r * 40 + q * 8], B + (long)(colBase + r) * ldb + c * 32 + q * 8);
        }
    };

#pragma unroll
    for (int s = 0; s < GSTAGES - 1; s++) {
        if (s < nCh) load_chunk(s, s);
        CP_COMMIT();
    }

    int st = 0;
    for (int c = 0; c < nCh; c++) {
        CP_WAIT(GSTAGES - 2);
        __syncthreads();

        int nc = c + GSTAGES - 1;
        if (nc < nCh) load_chunk(nc, nc % GSTAGES);
        CP_COMMIT();

        const __half* as = Asm + st * 128 * 40;
        const __half* bs = Bsm + st * 128 * 40;
#pragma unroll
        for (int kb = 0; kb < 2; kb++) {
            const int kk = kb * 16;
            unsigned af[4][4], bfr[4][2];
#pragma unroll
            for (int i = 0; i < 4; i++) {
                int r0 = warpM * 64 + i * 16 + grp;
                af[i][0] = *reinterpret_cast<const unsigned*>(&as[r0 * 40 + kk + tig * 2]);
                af[i][1] = *reinterpret_cast<const unsigned*>(&as[(r0 + 8) * 40 + kk + tig * 2]);
                af[i][2] = *reinterpret_cast<const unsigned*>(&as[r0 * 40 + kk + 8 + tig * 2]);
                af[i][3] = *reinterpret_cast<const unsigned*>(&as[(r0 + 8) * 40 + kk + 8 + tig * 2]);
            }
#pragma unroll
            for (int j = 0; j < 4; j++) {
                int c0 = warpN * 32 + j * 8 + grp;
                bfr[j][0] = *reinterpret_cast<const unsigned*>(&bs[c0 * 40 + kk + tig * 2]);
                bfr[j][1] = *reinterpret_cast<const unsigned*>(&bs[c0 * 40 + kk + 8 + tig * 2]);
            }
#pragma unroll
            for (int i = 0; i < 4; i++)
#pragma unroll
                for (int j = 0; j < 4; j++)
                    MMA16(acc[i][j][0], acc[i][j][1], acc[i][j][2], acc[i][j][3],
                          af[i][0], af[i][1], af[i][2], af[i][3], bfr[j][0], bfr[j][1]);
        }
        st = (st + 1 == GSTAGES) ? 0 : st + 1;
    }

    // ---- epilogue ----
    float* Cf = (float*)Cv;
    __half* Ch = (__half*)Cv;
#pragma unroll
    for (int i = 0; i < 4; i++) {
#pragma unroll
        for (int j = 0; j < 4; j++) {
            long row = rowBase + warpM * 64 + i * 16 + grp;
            int col = colBase + warpN * 32 + j * 8 + tig * 2;
#pragma unroll
            for (int half_ = 0; half_ < 2; half_++) {
                long r = row + half_ * 8;
                float v0 = acc[i][j][half_ * 2];
                float v1 = acc[i][j][half_ * 2 + 1];
                if (mode == 4) {
                    if (col < 2048) {
                        float qs = (col < 1024) ? 0.125f : 1.f;
                        *reinterpret_cast<__half2*>(&qh[r * 2048 + col]) =
                            __floats2half2_rn(v0 * qs, v1 * qs);
                    } else {
                        int hh = (col - 2048) >> 6;
                        int hd = (col - 2048) & 63;
                        int bb = (int)(r >> 11), ss = (int)(r & 2047);
                        __half* base = vth + (((long)(bb * H_ + hh) * HD_ + hd)) * S_ + ss;
                        base[0]  = __float2half_rn(v0);
                        base[S_] = __float2half_rn(v1);
                    }
                } else if (mode == 1) {
                    *reinterpret_cast<__half2*>(&Ch[r * ldc + col]) =
                        __floats2half2_rn(gelu_tanh(v0 + evec[col]),
                                          gelu_tanh(v1 + evec[col + 1]));
                } else if (mode == 2) {
                    int bb = (int)(r >> 11);
                    v0 = EX[r * ldc + col] + ada[bb * 6 * D_ + adaOff + col] * v0;
                    v1 = EX[r * ldc + col + 1] + ada[bb * 6 * D_ + adaOff + col + 1] * v1;
                    *reinterpret_cast<float2*>(&Cf[r * ldc + col]) = make_float2(v0, v1);
                } else {  // mode 3
                    int bb = (int)(r >> 11);
                    v0 = EX[r * ldc + col] + ada[bb * 6 * D_ + adaOff + col] * (v0 + evec[col]);
                    v1 = EX[r * ldc + col + 1] + ada[bb * 6 * D_ + adaOff + col + 1] * (v1 + evec[col + 1]);
                    *reinterpret_cast<float2*>(&Cf[r * ldc + col]) = make_float2(v0, v1);
                }
            }
        }
    }
}

// ---------------- adaLN ----------------
__global__ void __launch_bounds__(256) ada_kernel(
    const float* __restrict__ c, const float* __restrict__ w,
    const float* __restrict__ bias, float* __restrict__ out)
{
    int warp = (blockIdx.x * blockDim.x + threadIdx.x) >> 5;
    int lane = threadIdx.x & 31;
    if (warp >= 6 * D_) return;
    const float* wr = w + (long)warp * D_;
    float s0 = 0.f, s1 = 0.f;
    for (int d = lane; d < D_; d += 32) {
        float wv = wr[d];
        s0 += c[d] * wv;
        s1 += c[D_ + d] * wv;
    }
#pragma unroll
    for (int o = 16; o > 0; o >>= 1) {
        s0 += __shfl_down_sync(0xffffffffu, s0, o);
        s1 += __shfl_down_sync(0xffffffffu, s1, o);
    }
    if (lane == 0) {
        out[warp] = s0 + bias[warp];
        out[6 * D_ + warp] = s1 + bias[warp];
    }
}

// ---------------- LayerNorm + modulate, fp16 output ----------------
__global__ void __launch_bounds__(256) ln_mod_kernel(
    const float* __restrict__ x, const float* __restrict__ w,
    const float* __restrict__ ada, int shOff, int scOff, __half* __restrict__ h)
{
    int r = blockIdx.x;
    int b = r >> 11;
    const float* xr = x + (long)r * D_;
    int tid = threadIdx.x;
    float s = 0.f, ss = 0.f;
    float vals[4];
#pragma unroll
    for (int i = 0; i < 4; i++) {
        float v = xr[tid + i * 256];
        vals[i] = v; s += v; ss += v * v;
    }
    __shared__ float rs[256], rss[256];
    rs[tid] = s; rss[tid] = ss;
    __syncthreads();
    for (int st = 128; st > 0; st >>= 1) {
        if (tid < st) { rs[tid] += rs[tid + st]; rss[tid] += rss[tid + st]; }
        __syncthreads();
    }
    float mean = rs[0] * (1.f / D_);
    float var = rss[0] * (1.f / D_) - mean * mean;
    float inv = rsqrtf(var + 1e-5f);
    const float* sh = ada + b * 6 * D_ + shOff;
    const float* sc = ada + b * 6 * D_ + scOff;
#pragma unroll
    for (int i = 0; i < 4; i++) {
        int d = tid + i * 256;
        h[(long)r * D_ + d] =
            __float2half_rn((vals[i] - mean) * inv * w[d] * (1.f + sc[d]) + sh[d]);
    }
}

// ---------------- launch ----------------
extern "C" void kernel_launch(void* const* d_in, const int* in_sizes, int n_in,
                              void* d_out, int out_size)
{
    (void)in_sizes; (void)n_in; (void)out_size;
    const float* x       = (const float*)d_in[0];
    const float* c       = (const float*)d_in[3];
    const float* norm1_w = (const float*)d_in[4];
    const float* w_qkv   = (const float*)d_in[5];
    const float* w_out   = (const float*)d_in[6];
    const float* norm2_w = (const float*)d_in[7];
    const float* mlp_w1  = (const float*)d_in[8];
    const float* mlp_b1  = (const float*)d_in[9];
    const float* mlp_w2  = (const float*)d_in[10];
    const float* mlp_b2  = (const float*)d_in[11];
    const float* ada_w   = (const float*)d_in[12];
    const float* ada_b   = (const float*)d_in[13];
    float* out = (float*)d_out;

    float *ada, *x1;
    __half *h, *qkh, *vt, *attn2, *mlp, *wqkv_h, *wout_h, *w1_h, *w2_h;
    cudaGetSymbolAddress((void**)&ada,    g_ada);
    cudaGetSymbolAddress((void**)&h,      g_h);
    cudaGetSymbolAddress((void**)&qkh,    g_qkh);
    cudaGetSymbolAddress((void**)&vt,     g_vt);
    cudaGetSymbolAddress((void**)&attn2,  g_attn2);
    cudaGetSymbolAddress((void**)&x1,     g_x1);
    cudaGetSymbolAddress((void**)&mlp,    g_mlp);
    cudaGetSymbolAddress((void**)&wqkv_h, g_wqkv);
    cudaGetSymbolAddress((void**)&wout_h, g_wout);
    cudaGetSymbolAddress((void**)&w1_h,   g_w1);
    cudaGetSymbolAddress((void**)&w2_h,   g_w2);

    static int inited = 0;
    if (!inited) {
        cudaFuncSetAttribute(flash_attn, cudaFuncAttributeMaxDynamicSharedMemorySize, FA_SMEM);
        cudaFuncSetAttribute(gemm_nt_f16, cudaFuncAttributeMaxDynamicSharedMemorySize, GEMM_SMEM);
        inited = 1;
    }

    // 0. convert weights to fp16 (single launch)
    conv_all<<<12 * D_ * D_ / 4 / 256, 256>>>(w_qkv, w_out, mlp_w1, mlp_w2,
                                              wqkv_h, wout_h, w1_h, w2_h);
    // 1. adaLN projection
    ada_kernel<<<768, 256>>>(c, ada_w, ada_b, ada);
    // 2. LN1 + modulate -> fp16 h
    ln_mod_kernel<<<B_ * S_, 256>>>(x, norm1_w, ada, 0, D_, h);
    // 3. QKV GEMM -> Q(x1/8),K fp16 + V^T fp16
    gemm_nt_f16<<<dim3(24, 32), 256, GEMM_SMEM>>>(h, wqkv_h, nullptr, D_,
                                                  D_, D_, 0, 4,
                                                  nullptr, nullptr, nullptr, 0,
                                                  qkh, vt);
    // 4. flash attention (fp16 mma) -> attn2 fp16
    flash_attn<<<dim3(S_ / 256, B_ * H_), 512, FA_SMEM>>>(qkh, vt, attn2);
    // 5. out-proj + residual1 (fp32 out)
    gemm_nt_f16<<<dim3(8, 32), 256, GEMM_SMEM>>>(attn2, wout_h, x1, D_,
                                                 D_, D_, D_, 2,
                                                 x, nullptr, ada, 2 * D_,
                                                 nullptr, nullptr);
    // 6. LN2 + modulate -> fp16 h
    ln_mod_kernel<<<B_ * S_, 256>>>(x1, norm2_w, ada, 3 * D_, 4 * D_, h);
    // 7. MLP1 + bias + gelu -> fp16 mlp
    gemm_nt_f16<<<dim3(32, 32), 256, GEMM_SMEM>>>(h, w1_h, mlp, D_,
                                                  D_, D_, 4 * D_, 1,
                                                  nullptr, mlp_b1, nullptr, 0,
                                                  nullptr, nullptr);
    // 8. MLP2 + final residual (fp32 out)
    gemm_nt_f16<<<dim3(8, 32), 256, GEMM_SMEM>>>(mlp, w2_h, out, 4 * D_,
                                                 4 * D_, 4 * D_, D_, 3,
                                                 x1, mlp_b2, ada, 5 * D_,
                                                 nullptr, nullptr);
}